// round 6
// baseline (speedup 1.0000x reference)
#include <cuda_runtime.h>

// Problem constants
constexpr int C   = 128;   // original channels
constexpr int CF  = 16;    // conv-out channels (C/8)
constexpr int N   = 256;   // pixels per patch (16x16)
constexpr int K   = 15;    // top-k
constexpr int K2  = 18;    // fp32 superset size for pass 1
constexpr int TPB = 256;   // one thread per pixel

constexpr int XO_PITCH = 129;  // padded pitch for [N][C] patch tile (conflict-free)
constexpr int XN_PITCH = 20;   // padded pitch for [N][18] feature rows (80B, float4-aligned)

// shared memory layout (bytes). nrmd (doubles) first for 8B alignment.
constexpr int OFF_NRMD = 0;                               // 256 doubles = 2048 B
constexpr int OFF_XO   = 2048;                            // floats: 256*129*4 = 132096 B
constexpr int OFF_FW   = OFF_XO + N * XO_PITCH * 4;       // 16*128*4 = 8192 B
constexpr int OFF_FB   = OFF_FW + CF * C * 4;             // 64 B
constexpr int OFF_XNF  = OFF_FB + CF * 4;                 // normalized feats f32: 256*20*4 = 20480 B
constexpr int OFF_ACC  = OFF_XNF + N * XN_PITCH * 4;      // raw feats f32:        20480 B
constexpr int SMEM_BYTES = OFF_ACC + N * XN_PITCH * 4;    // = 183360 B (~179 KB)

__global__ void __launch_bounds__(TPB, 1)
gnn_local_cluster_kernel(const float* __restrict__ x_in,
                         const float* __restrict__ f_w,
                         const float* __restrict__ f_b,
                         const float* __restrict__ edge_alpha,
                         const float* __restrict__ edge_beta,
                         float* __restrict__ out)
{
    extern __shared__ char smraw[];
    double* nrmd = reinterpret_cast<double*>(smraw + OFF_NRMD); // [N] fp64 row norms
    float*  xo   = reinterpret_cast<float*>(smraw + OFF_XO);    // [N][129] original channels
    float*  fw   = reinterpret_cast<float*>(smraw + OFF_FW);    // [16][128]
    float*  fb   = reinterpret_cast<float*>(smraw + OFF_FB);    // [16]
    float*  xnf  = reinterpret_cast<float*>(smraw + OFF_XNF);   // [N][20] normalized (f32 view)
    float*  accf = reinterpret_cast<float*>(smraw + OFF_ACC);   // [N][20] pre-norm feats (f32)

    const int p   = blockIdx.x;          // patch id = (b*7 + wg)*7 + hg
    const int b   = p / 49;
    const int wg  = (p / 7) % 7;
    const int hg  = p % 7;
    const int tid = threadIdx.x;

    // global element (c,i,j) of this patch: gbase + c*112*112 + i*112 + j
    const int gbase = ((b * C * 112) + wg * 16) * 112 + hg * 16;

    // ---- load weights ----
    for (int idx = tid; idx < CF * C; idx += TPB) fw[idx] = f_w[idx];
    if (tid < CF) fb[tid] = f_b[tid];

    // ---- load patch tile into smem, pixel-major [n][c] ----
    for (int idx = tid; idx < C * N; idx += TPB) {
        int c = idx >> 8;
        int n = idx & 255;
        int i = n >> 4, j = n & 15;
        xo[n * XO_PITCH + c] = x_in[gbase + c * (112 * 112) + i * 112 + j];
    }
    __syncthreads();

    // ---- phase B: 1x1 conv (fp32) + grid augment + fp64-exact L2 normalize ----
    {
        const int n = tid;
        float acc[CF];
        #pragma unroll
        for (int d = 0; d < CF; ++d) acc[d] = 0.0f;
        const float* xr = xo + n * XO_PITCH;
        for (int c = 0; c < C; ++c) {
            float xv = xr[c];                          // conflict-free (pad 129)
            #pragma unroll
            for (int d = 0; d < CF; ++d)
                acc[d] = __fmaf_rn(xv, fw[d * C + c], acc[d]);   // broadcast LDS
        }
        #pragma unroll
        for (int d = 0; d < CF; ++d) acc[d] = __fadd_rn(acc[d], fb[d]);

        // grid values in fp32, matching the reference ops exactly
        // (sum of squares 5440 is exact in fp32 regardless of reduction order)
        const int i = n >> 4, j = n & 15;
        const float sd    = __fsqrt_rn(__fdiv_rn(5440.0f, 255.0f));
        const float denom = __fadd_rn(sd, 1e-5f);
        const float g0 = __fdiv_rn((float)i - 7.5f, denom);
        const float g1 = __fdiv_rn((float)j - 7.5f, denom);

        // fp64 norm of the 18-dim augmented row (exact given fp32 inputs)
        double ss = 0.0;
        #pragma unroll
        for (int d = 0; d < CF; ++d) ss = fma((double)acc[d], (double)acc[d], ss);
        ss = fma((double)g0, (double)g0, ss);
        ss = fma((double)g1, (double)g1, ss);
        double nd = sqrt(ss);
        if (nd < 1e-8) nd = 1e-8;
        nrmd[n] = nd;

        float* aw = accf + n * XN_PITCH;
        float* xw = xnf  + n * XN_PITCH;
        #pragma unroll
        for (int d = 0; d < CF; ++d) {
            aw[d] = acc[d];
            xw[d] = (float)((double)acc[d] / nd);
        }
        aw[16] = g0;  aw[17] = g1;  aw[18] = 0.0f;  aw[19] = 0.0f;
        xw[16] = (float)((double)g0 / nd);
        xw[17] = (float)((double)g1 / nd);
        xw[18] = 0.0f;  xw[19] = 0.0f;
    }
    __syncthreads();

    // ---- pass 1: fp32 sims, keep top-18 superset (thread = row n) ----
    const int n = tid;
    float rreg[18];
    {
        const float* xr = xnf + n * XN_PITCH;
        #pragma unroll
        for (int d = 0; d < 18; ++d) rreg[d] = xr[d];
    }

    float bv[K2];
    int   bi[K2];
    #pragma unroll
    for (int k = 0; k < K2; ++k) { bv[k] = -1e30f; bi[k] = 0; }

    for (int m = 0; m < N; ++m) {
        const float4* xm4 = reinterpret_cast<const float4*>(xnf + m * XN_PITCH);
        float4 v0 = xm4[0], v1 = xm4[1], v2 = xm4[2], v3 = xm4[3];  // broadcast LDS.128
        float2 v4 = *reinterpret_cast<const float2*>(xnf + m * XN_PITCH + 16);
        float s = 0.0f;
        s = __fmaf_rn(rreg[0],  v0.x, s); s = __fmaf_rn(rreg[1],  v0.y, s);
        s = __fmaf_rn(rreg[2],  v0.z, s); s = __fmaf_rn(rreg[3],  v0.w, s);
        s = __fmaf_rn(rreg[4],  v1.x, s); s = __fmaf_rn(rreg[5],  v1.y, s);
        s = __fmaf_rn(rreg[6],  v1.z, s); s = __fmaf_rn(rreg[7],  v1.w, s);
        s = __fmaf_rn(rreg[8],  v2.x, s); s = __fmaf_rn(rreg[9],  v2.y, s);
        s = __fmaf_rn(rreg[10], v2.z, s); s = __fmaf_rn(rreg[11], v2.w, s);
        s = __fmaf_rn(rreg[12], v3.x, s); s = __fmaf_rn(rreg[13], v3.y, s);
        s = __fmaf_rn(rreg[14], v3.z, s); s = __fmaf_rn(rreg[15], v3.w, s);
        s = __fmaf_rn(rreg[16], v4.x, s); s = __fmaf_rn(rreg[17], v4.y, s);

        if (s > bv[K2 - 1]) {
            int si = m;
            #pragma unroll
            for (int k2 = 0; k2 < K2; ++k2) {
                if (s > bv[k2]) {
                    float tv = bv[k2]; bv[k2] = s;  s  = tv;
                    int   ti = bi[k2]; bi[k2] = si; si = ti;
                }
            }
        }
    }

    // ---- pass 2: fp64 re-rank of the 18 candidates -> true top-15 ----
    double rregd[18];
    {
        const float* ar = accf + n * XN_PITCH;
        #pragma unroll
        for (int d = 0; d < 18; ++d) rregd[d] = (double)ar[d];
    }
    const double ninv_n = nrmd[n];

    double dbv[K];
    int    dbi[K];
    #pragma unroll
    for (int k = 0; k < K; ++k) { dbv[k] = -1e300; dbi[k] = 0; }

    #pragma unroll
    for (int t = 0; t < K2; ++t) {
        const int m = bi[t];
        const float* am = accf + m * XN_PITCH;
        double s = 0.0;
        #pragma unroll
        for (int d = 0; d < 18; ++d) s = fma(rregd[d], (double)am[d], s);
        s = s / (ninv_n * nrmd[m]);

        if (s > dbv[K - 1]) {
            double sv = s; int si = m;
            #pragma unroll
            for (int k2 = 0; k2 < K; ++k2) {
                if (sv > dbv[k2]) {
                    double tv = dbv[k2]; dbv[k2] = sv; sv = tv;
                    int    ti = dbi[k2]; dbi[k2] = si; si = ti;
                }
            }
        }
    }

    // ---- edge weights: sigmoid then softmax over the K edges ----
    const float alpha = edge_alpha[0];
    const float beta  = edge_beta[0];
    float wn_[K];
    float wmax = -1e30f;
    #pragma unroll
    for (int k = 0; k < K; ++k) {
        float z  = __fadd_rn(beta, __fmul_rn(alpha, (float)dbv[k]));
        float wv = __fdiv_rn(1.0f, __fadd_rn(1.0f, expf(-z)));
        wn_[k] = wv;
        wmax = fmaxf(wmax, wv);
    }
    float wsum = 0.0f;
    #pragma unroll
    for (int k = 0; k < K; ++k) {
        wn_[k] = expf(__fadd_rn(wn_[k], -wmax));
        wsum = __fadd_rn(wsum, wn_[k]);
    }
    #pragma unroll
    for (int k = 0; k < K; ++k) wn_[k] = __fdiv_rn(wn_[k], wsum);

    int basek[K];
    #pragma unroll
    for (int k = 0; k < K; ++k) basek[k] = dbi[k] * XO_PITCH;

    // ---- gather original channels from top-k neighbors, write out ----
    const int i = n >> 4, j = n & 15;
    float* outp = out + gbase + i * 112 + j;   // + c*112*112 per channel
    for (int c = 0; c < C; ++c) {
        float o = 0.0f;
        #pragma unroll
        for (int k = 0; k < K; ++k)
            o = __fmaf_rn(wn_[k], xo[basek[k] + c], o);
        outp[c * (112 * 112)] = o;
    }
}

extern "C" void kernel_launch(void* const* d_in, const int* in_sizes, int n_in,
                              void* d_out, int out_size) {
    const float* x_in = (const float*)d_in[0];
    const float* f_w  = (const float*)d_in[1];
    const float* f_b  = (const float*)d_in[2];
    const float* ea   = (const float*)d_in[3];
    const float* eb   = (const float*)d_in[4];
    float* out = (float*)d_out;

    cudaFuncSetAttribute(gnn_local_cluster_kernel,
                         cudaFuncAttributeMaxDynamicSharedMemorySize, SMEM_BYTES);
    gnn_local_cluster_kernel<<<196, TPB, SMEM_BYTES>>>(x_in, f_w, f_b, ea, eb, out);
}